// round 6
// baseline (speedup 1.0000x reference)
#include <cuda_runtime.h>
#include <cuda_bf16.h>
#include <cstdint>

// Problem constants (from reference)
#define OUTF    11008
#define INF     4096
#define NGROUPS 32      // INF / 128
#define GSIZE   128
#define BATCH   8

#define THREADS 256
#define WARPS   (THREADS / 32)          // 8
#define NOUT    4                       // output rows per warp
#define OUT_PER_BLOCK (WARPS * NOUT)    // 32
#define GRID    (OUTF / OUT_PER_BLOCK)  // 344

__device__ __forceinline__ float bf16_rn(float v) {
    return __bfloat162float(__float2bfloat16_rn(v));
}

__global__ __launch_bounds__(THREADS)
void wo4l_kernel(const float* __restrict__ x,      // f32 (bf16-valued), [8][4096]
                 const int* __restrict__ qw,       // int32 codes 0..15, [11008][4096]
                 const float2* __restrict__ sz,    // f32 {scale, zero}, [32][11008]
                 float* __restrict__ out)          // f32 (bf16-valued), [8][11008]
{
    const int warp  = threadIdx.x >> 5;
    const int lane  = threadIdx.x & 31;
    const int obase = blockIdx.x * OUT_PER_BLOCK + warp * NOUT;

    const int4*   qp = (const int4*)qw;    // 4 codes per load; k = 4*idx
    const float4* xp = (const float4*)x;   // 4 x-values per load

    float acc[NOUT][BATCH];
    #pragma unroll
    for (int n = 0; n < NOUT; n++)
        #pragma unroll
        for (int b = 0; b < BATCH; b++)
            acc[n][b] = 0.0f;

    // prefetch group 0's q codes (this lane's k = g*128 + lane*4 .. +3)
    int4 qv[NOUT];
    #pragma unroll
    for (int n = 0; n < NOUT; n++)
        qv[n] = __ldcs(&qp[(size_t)(obase + n) * (INF / 4) + lane]);

    for (int g = 0; g < NGROUPS; ++g) {
        // prefetch next group's q codes (covers DRAM latency)
        int4 qn[NOUT];
        if (g + 1 < NGROUPS) {
            #pragma unroll
            for (int n = 0; n < NOUT; n++)
                qn[n] = __ldcs(&qp[(size_t)(obase + n) * (INF / 4) + (g + 1) * 32 + lane]);
        }

        // per-group scale/zero for the warp's 4 rows (uniform across lanes)
        float s[NOUT], m8s[NOUT];
        __nv_bfloat16 zb[NOUT];
        #pragma unroll
        for (int n = 0; n < NOUT; n++) {
            float2 v = __ldg(&sz[(size_t)g * OUTF + obase + n]);
            s[n]   = v.x;                          // bf16-exact scale
            m8s[n] = -8.0f * v.x;                  // exact power-of-2 multiple
            zb[n]  = __float2bfloat16_rn(v.y);     // zero as bf16 (identity round)
        }

        // x for this lane's 4 k-values, all 8 batches (f32, L1/L2-resident)
        float xe[BATCH][4];
        #pragma unroll
        for (int b = 0; b < BATCH; b++) {
            float4 xv = __ldg(&xp[(size_t)b * (INF / 4) + g * 32 + lane]);
            xe[b][0] = bf16_rn(xv.x);
            xe[b][1] = bf16_rn(xv.y);
            xe[b][2] = bf16_rn(xv.z);
            xe[b][3] = bf16_rn(xv.w);
        }

        #pragma unroll
        for (int j = 0; j < 4; ++j) {
            float w[NOUT];
            #pragma unroll
            for (int n = 0; n < NOUT; n++) {
                const int q = (j == 0) ? qv[n].x : (j == 1) ? qv[n].y
                            : (j == 2) ? qv[n].z : qv[n].w;
                // (q-8)*s exact in f32, RN->bf16 (ref's bf16 multiply),
                // then bf16 add of zero (ref's bf16 add).
                const float t = fmaf((float)q, s[n], m8s[n]);
                const __nv_bfloat16 wb = __hadd(__float2bfloat16_rn(t), zb[n]);
                w[n] = __bfloat162float(wb);
            }
            #pragma unroll
            for (int b = 0; b < BATCH; b++)
                #pragma unroll
                for (int n = 0; n < NOUT; n++)
                    acc[n][b] = fmaf(w[n], xe[b][j], acc[n][b]);
        }

        #pragma unroll
        for (int n = 0; n < NOUT; n++) qv[n] = qn[n];
    }

    // warp reduction: each lane holds the partial over its k-slice
    #pragma unroll
    for (int m = 16; m >= 1; m >>= 1)
        #pragma unroll
        for (int n = 0; n < NOUT; n++)
            #pragma unroll
            for (int b = 0; b < BATCH; b++)
                acc[n][b] += __shfl_xor_sync(0xffffffffu, acc[n][b], m);

    // epilogue: lane b stores batch b; round to bf16 (reference output is
    // bf16-valued), store as f32.
    #pragma unroll
    for (int b = 0; b < BATCH; b++) {
        if (lane == b) {
            #pragma unroll
            for (int n = 0; n < NOUT; n++)
                out[(size_t)b * OUTF + obase + n] = bf16_rn(acc[n][b]);
        }
    }
}

extern "C" void kernel_launch(void* const* d_in, const int* in_sizes, int n_in,
                              void* d_out, int out_size)
{
    // Route inputs by element count (order-proof); fall back to positional.
    const float*  x  = nullptr;   // 8*4096      = 32768
    const int*    qw = nullptr;   // 11008*4096  = 45088768
    const float2* sz = nullptr;   // 32*11008*2  = 704512 scalars
    for (int i = 0; i < n_in; i++) {
        if      (in_sizes[i] == BATCH * INF)         x  = (const float*)d_in[i];
        else if (in_sizes[i] == OUTF * INF)          qw = (const int*)d_in[i];
        else if (in_sizes[i] == NGROUPS * OUTF * 2)  sz = (const float2*)d_in[i];
    }
    if (!x || !qw || !sz) {
        x  = (const float*)d_in[0];
        qw = (const int*)d_in[1];
        sz = (const float2*)d_in[2];
    }
    float* out = (float*)d_out;

    wo4l_kernel<<<GRID, THREADS>>>(x, qw, sz, out);
}

// round 7
// speedup vs baseline: 2.0863x; 2.0863x over previous
#include <cuda_runtime.h>
#include <cuda_bf16.h>
#include <cstdint>

// Problem constants (from reference)
#define OUTF    11008
#define INF     4096
#define NGROUPS 32      // INF / 128
#define GSIZE   128
#define BATCH   8

#define THREADS 256
#define WARPS   (THREADS / 32)          // 8
#define NOUT    2                       // output rows per warp
#define OUT_PER_BLOCK (WARPS * NOUT)    // 16
#define GRID    (OUTF / OUT_PER_BLOCK)  // 688

__device__ __forceinline__ float bf16_rn(float v) {
    return __bfloat162float(__float2bfloat16_rn(v));
}

__global__ __launch_bounds__(THREADS, 4)
void wo4l_kernel(const float* __restrict__ x,      // f32 (bf16-valued), [8][4096]
                 const int* __restrict__ qw,       // int32 codes 0..15, [11008][4096]
                 const float2* __restrict__ sz,    // f32 {scale, zero}, [32][11008]
                 float* __restrict__ out)          // f32 (bf16-valued), [8][11008]
{
    const int warp = threadIdx.x >> 5;
    const int lane = threadIdx.x & 31;
    const int o0   = blockIdx.x * OUT_PER_BLOCK + warp * NOUT;

    const int4*   qp = (const int4*)qw;    // 4 codes per load; lane's k = g*128+lane*4+j
    const float2* xp = (const float2*)x;   // 2 x-values per load

    float acc[NOUT][BATCH];
    #pragma unroll
    for (int n = 0; n < NOUT; n++)
        #pragma unroll
        for (int b = 0; b < BATCH; b++)
            acc[n][b] = 0.0f;

    for (int g = 0; g < NGROUPS; ++g) {
        // per-group scale/zero for the warp's 2 rows (uniform across lanes)
        float s[NOUT], m8s[NOUT];
        __nv_bfloat162 z2[NOUT];
        #pragma unroll
        for (int n = 0; n < NOUT; n++) {
            const float2 v = __ldg(&sz[(size_t)g * OUTF + o0 + n]);
            s[n]   = v.x;                                  // bf16-exact scale
            m8s[n] = -8.0f * v.x;                          // exact
            z2[n]  = __bfloat162bfloat162(__float2bfloat16_rn(v.y)); // {z,z}
        }

        // q codes for this group (streaming; read exactly once)
        int4 qv[NOUT];
        #pragma unroll
        for (int n = 0; n < NOUT; n++)
            qv[n] = __ldcs(&qp[(size_t)(o0 + n) * (INF / 4) + g * 32 + lane]);

        #pragma unroll
        for (int jp = 0; jp < 2; ++jp) {
            // dequant 2 codes per row with bit-exact double bf16 rounding
            float wa[NOUT], wb[NOUT];
            #pragma unroll
            for (int n = 0; n < NOUT; n++) {
                const int qa = jp ? qv[n].z : qv[n].x;
                const int qb = jp ? qv[n].w : qv[n].y;
                const float ta = fmaf((float)qa, s[n], m8s[n]);  // exact (q-8)*s
                const float tb = fmaf((float)qb, s[n], m8s[n]);
                const __nv_bfloat162 w2 = __hadd2(__floats2bfloat162_rn(ta, tb), z2[n]);
                wa[n] = __bfloat162float(__low2bfloat16(w2));
                wb[n] = __bfloat162float(__high2bfloat16(w2));
            }

            // x for the two k's of this half, all 8 batches (f32, L1-resident;
            // x is already bf16-valued — no rounding needed)
            #pragma unroll
            for (int b = 0; b < BATCH; b++) {
                const float2 xv = __ldg(&xp[(size_t)b * (INF / 2) + g * 64 + lane * 2 + jp]);
                #pragma unroll
                for (int n = 0; n < NOUT; n++) {
                    acc[n][b] = fmaf(wa[n], xv.x, acc[n][b]);
                    acc[n][b] = fmaf(wb[n], xv.y, acc[n][b]);
                }
            }
        }
    }

    // warp reduction: each lane holds the partial over its k-slice
    #pragma unroll
    for (int m = 16; m >= 1; m >>= 1)
        #pragma unroll
        for (int n = 0; n < NOUT; n++)
            #pragma unroll
            for (int b = 0; b < BATCH; b++)
                acc[n][b] += __shfl_xor_sync(0xffffffffu, acc[n][b], m);

    // epilogue: lane b stores batch b; bf16-round (ref output is bf16-valued)
    #pragma unroll
    for (int b = 0; b < BATCH; b++) {
        if (lane == b) {
            #pragma unroll
            for (int n = 0; n < NOUT; n++)
                out[(size_t)b * OUTF + o0 + n] = bf16_rn(acc[n][b]);
        }
    }
}

extern "C" void kernel_launch(void* const* d_in, const int* in_sizes, int n_in,
                              void* d_out, int out_size)
{
    // Route inputs by element count (order-proof); fall back to positional.
    const float*  x  = nullptr;   // 8*4096      = 32768
    const int*    qw = nullptr;   // 11008*4096  = 45088768
    const float2* sz = nullptr;   // 32*11008*2  = 704512 scalars
    for (int i = 0; i < n_in; i++) {
        if      (in_sizes[i] == BATCH * INF)         x  = (const float*)d_in[i];
        else if (in_sizes[i] == OUTF * INF)          qw = (const int*)d_in[i];
        else if (in_sizes[i] == NGROUPS * OUTF * 2)  sz = (const float2*)d_in[i];
    }
    if (!x || !qw || !sz) {
        x  = (const float*)d_in[0];
        qw = (const int*)d_in[1];
        sz = (const float2*)d_in[2];
    }
    float* out = (float*)d_out;

    wo4l_kernel<<<GRID, THREADS>>>(x, qw, sz, out);
}

// round 8
// speedup vs baseline: 3.8083x; 1.8253x over previous
#include <cuda_runtime.h>
#include <cuda_bf16.h>
#include <cstdint>

// Problem constants (from reference)
#define OUTF    11008
#define INF     4096
#define NGROUPS 32      // INF / 128
#define GSIZE   128
#define BATCH   8

#define THREADS 128
#define WARPS   (THREADS / 32)          // 4
#define NOUT    4                       // output rows per warp
#define OUT_PER_BLOCK (WARPS * NOUT)    // 16
#define GRID    (OUTF / OUT_PER_BLOCK)  // 688

typedef unsigned long long ull;

// ---- packed f32x2 helpers (Blackwell FFMA2; PTX-only) ----
__device__ __forceinline__ ull pack2(uint32_t lo, uint32_t hi) {
    ull r; asm("mov.b64 %0, {%1, %2};" : "=l"(r) : "r"(lo), "r"(hi)); return r;
}
__device__ __forceinline__ ull ffma2(ull a, ull b, ull c) {
    ull d; asm("fma.rn.f32x2 %0, %1, %2, %3;" : "=l"(d) : "l"(a), "l"(b), "l"(c)); return d;
}
__device__ __forceinline__ void unpack2(ull v, float& lo, float& hi) {
    asm("mov.b64 {%0, %1}, %2;" : "=f"(lo), "=f"(hi) : "l"(v));
}
__device__ __forceinline__ float bf16_rn(float v) {
    return __bfloat162float(__float2bfloat16_rn(v));
}

// 64 KB scratch: x transposed/packed. Entry i = (g*4+j)*32 + lane holds
// all 8 batches (bf16) of x at k = g*128 + lane*4 + j.
__device__ __align__(16) uint4 g_xt[INF];

__global__ void xt_kernel(const float* __restrict__ x) {
    const int i = blockIdx.x * blockDim.x + threadIdx.x;   // 0..4095
    if (i >= INF) return;
    const int lane = i & 31;
    const int gj   = i >> 5;
    const int g    = gj >> 2;
    const int j    = gj & 3;
    const int k    = g * GSIZE + lane * 4 + j;
    uint32_t u[4];
    #pragma unroll
    for (int bp = 0; bp < 4; bp++) {
        const float f0 = x[(size_t)(2 * bp) * INF + k];
        const float f1 = x[(size_t)(2 * bp + 1) * INF + k];
        __nv_bfloat162 p = __floats2bfloat162_rn(f0, f1);   // exact: values are bf16-valued
        u[bp] = *reinterpret_cast<uint32_t*>(&p);           // {b_even lo16, b_odd hi16}
    }
    g_xt[i] = make_uint4(u[0], u[1], u[2], u[3]);
}

__global__ __launch_bounds__(THREADS)
void wo4l_kernel(const int* __restrict__ qw,       // int32 codes 0..15, [11008][4096]
                 const float2* __restrict__ sz,    // f32 {scale, zero}, [32][11008]
                 float* __restrict__ out)          // f32 (bf16-valued), [8][11008]
{
    const int warp = threadIdx.x >> 5;
    const int lane = threadIdx.x & 31;
    const int o0   = blockIdx.x * OUT_PER_BLOCK + warp * NOUT;

    const int4* qp = (const int4*)qw;   // lane's k-slice: g*128 + lane*4 + 0..3

    ull acc[NOUT][4];                   // [row][batch-pair] packed f32x2
    #pragma unroll
    for (int n = 0; n < NOUT; n++)
        #pragma unroll
        for (int bp = 0; bp < 4; bp++)
            acc[n][bp] = 0ull;

    // prefetch group 0's q codes
    int4 qv[NOUT];
    #pragma unroll
    for (int n = 0; n < NOUT; n++)
        qv[n] = __ldcs(&qp[(size_t)(o0 + n) * (INF / 4) + lane]);

    for (int g = 0; g < NGROUPS; ++g) {
        // prefetch next group's q (covers DRAM latency)
        int4 qn[NOUT];
        if (g + 1 < NGROUPS) {
            #pragma unroll
            for (int n = 0; n < NOUT; n++)
                qn[n] = __ldcs(&qp[(size_t)(o0 + n) * (INF / 4) + (g + 1) * 32 + lane]);
        }

        // per-group scale/zero (uniform across lanes; L1 broadcast)
        float s[NOUT], m8s[NOUT];
        __nv_bfloat162 z2[NOUT];
        #pragma unroll
        for (int n = 0; n < NOUT; n++) {
            const float2 v = __ldg(&sz[(size_t)g * OUTF + o0 + n]);
            s[n]   = v.x;
            m8s[n] = -8.0f * v.x;                                    // exact
            z2[n]  = __bfloat162bfloat162(__float2bfloat16_rn(v.y)); // {z,z}
        }

        // k-pairs: jp=0 -> (j0,j1)=(0,1), jp=1 -> (2,3)
        #pragma unroll
        for (int jp = 0; jp < 2; ++jp) {
            // x for the two k's: one LDG.128 each = all 8 batches (bf16-packed)
            const uint4 xa = g_xt[(g * 4 + 2 * jp)     * 32 + lane];
            const uint4 xb = g_xt[(g * 4 + 2 * jp + 1) * 32 + lane];
            ull x2a[4], x2b[4];
            {
                const uint32_t ua[4] = {xa.x, xa.y, xa.z, xa.w};
                const uint32_t ub[4] = {xb.x, xb.y, xb.z, xb.w};
                #pragma unroll
                for (int bp = 0; bp < 4; bp++) {
                    x2a[bp] = pack2(ua[bp] << 16, ua[bp] & 0xffff0000u);
                    x2b[bp] = pack2(ub[bp] << 16, ub[bp] & 0xffff0000u);
                }
            }
            #pragma unroll
            for (int n = 0; n < NOUT; n++) {
                const int qa = jp ? qv[n].z : qv[n].x;
                const int qb = jp ? qv[n].w : qv[n].y;
                // exact (q-8)*s in f32, RN->bf16 (ref bf16 mul), bf16 add of zero
                const float ta = fmaf((float)qa, s[n], m8s[n]);
                const float tb = fmaf((float)qb, s[n], m8s[n]);
                const __nv_bfloat162 w2 = __hadd2(__floats2bfloat162_rn(ta, tb), z2[n]);
                const uint32_t w2u = *reinterpret_cast<const uint32_t*>(&w2);
                const uint32_t wau = w2u << 16;           // f32 bits of w(k=2jp)
                const uint32_t wbu = w2u & 0xffff0000u;   // f32 bits of w(k=2jp+1)
                const ull wa2 = pack2(wau, wau);
                const ull wb2 = pack2(wbu, wbu);
                #pragma unroll
                for (int bp = 0; bp < 4; bp++) {
                    acc[n][bp] = ffma2(wa2, x2a[bp], acc[n][bp]);
                    acc[n][bp] = ffma2(wb2, x2b[bp], acc[n][bp]);
                }
            }
        }

        #pragma unroll
        for (int n = 0; n < NOUT; n++) qv[n] = qn[n];
    }

    // unpack and warp-reduce
    float r[NOUT][BATCH];
    #pragma unroll
    for (int n = 0; n < NOUT; n++)
        #pragma unroll
        for (int bp = 0; bp < 4; bp++)
            unpack2(acc[n][bp], r[n][2 * bp], r[n][2 * bp + 1]);

    #pragma unroll
    for (int m = 16; m >= 1; m >>= 1)
        #pragma unroll
        for (int n = 0; n < NOUT; n++)
            #pragma unroll
            for (int b = 0; b < BATCH; b++)
                r[n][b] += __shfl_xor_sync(0xffffffffu, r[n][b], m);

    // epilogue: lane b stores batch b; bf16-round (ref output is bf16-valued)
    #pragma unroll
    for (int b = 0; b < BATCH; b++) {
        if (lane == b) {
            #pragma unroll
            for (int n = 0; n < NOUT; n++)
                out[(size_t)b * OUTF + o0 + n] = bf16_rn(r[n][b]);
        }
    }
}

extern "C" void kernel_launch(void* const* d_in, const int* in_sizes, int n_in,
                              void* d_out, int out_size)
{
    // Route inputs by element count (order-proof); fall back to positional.
    const float*  x  = nullptr;   // 8*4096      = 32768
    const int*    qw = nullptr;   // 11008*4096  = 45088768
    const float2* sz = nullptr;   // 32*11008*2  = 704512 scalars
    for (int i = 0; i < n_in; i++) {
        if      (in_sizes[i] == BATCH * INF)         x  = (const float*)d_in[i];
        else if (in_sizes[i] == OUTF * INF)          qw = (const int*)d_in[i];
        else if (in_sizes[i] == NGROUPS * OUTF * 2)  sz = (const float2*)d_in[i];
    }
    if (!x || !qw || !sz) {
        x  = (const float*)d_in[0];
        qw = (const int*)d_in[1];
        sz = (const float2*)d_in[2];
    }
    float* out = (float*)d_out;

    xt_kernel<<<INF / THREADS, THREADS>>>(x);
    wo4l_kernel<<<GRID, THREADS>>>(qw, sz, out);
}